// round 2
// baseline (speedup 1.0000x reference)
#include <cuda_runtime.h>
#include <cuda_bf16.h>
#include <math.h>

#define N1 50000
#define N2 199
#define FDIM 128
#define BGR 10
#define NPG 5000
#define KSEL 50
#define NFEAT (KSEL * N2)   // 9950

// ---------------- scratch (device globals; no allocation) ----------------
__device__ float g_msg1[N1 * FDIM];   // reused for layer1 & layer2 aggregation (graph1)
__device__ float g_h1  [N1 * FDIM];
__device__ float g_o1  [N1 * 64];
__device__ float g_cnt1[N1];
__device__ float g_msg2[N2 * FDIM];
__device__ float g_h2  [N2 * FDIM];
__device__ float g_o2  [N2 * 64];
__device__ float g_cnt2[N2];
__device__ float g_lastd[N1];
__device__ int   g_topk[BGR * KSEL];
__device__ float g_feat[BGR * NFEAT];
__device__ float g_z1raw[BGR * 128];

// ---------------- utility kernels ----------------
__global__ void zerok(float* p, int n) {
    int i = blockIdx.x * blockDim.x + threadIdx.x;
    if (i < n) p[i] = 0.f;
}

__global__ void countk(const int* __restrict__ dst, int e, float* cnt) {
    int i = blockIdx.x * blockDim.x + threadIdx.x;
    if (i < e) atomicAdd(&cnt[dst[i]], 1.0f);
}

// one warp per edge; each lane handles 4 consecutive features (float4 gather)
__global__ void scatterk(const float* __restrict__ x, const int* __restrict__ src,
                         const int* __restrict__ dst, int e, float* __restrict__ msg) {
    int idx  = blockIdx.x * blockDim.x + threadIdx.x;
    int edge = idx >> 5;
    if (edge >= e) return;
    int c = (idx & 31) * 4;
    int s = src[edge];
    int d = dst[edge];
    float4 v = *reinterpret_cast<const float4*>(x + (size_t)s * FDIM + c);
    float* m = msg + (size_t)d * FDIM + c;
    atomicAdd(m + 0, v.x);
    atomicAdd(m + 1, v.y);
    atomicAdd(m + 2, v.z);
    atomicAdd(m + 3, v.w);
}

// ---------------- SAGE linear: out = relu(mean @ wl^T + bl + x @ wr^T) ----------------
// 256 threads, 32 nodes/block, smem-tiled over k in chunks of 32, padded to kill bank conflicts.
template <int FOUT>
__global__ void sage_linear(const float* __restrict__ msg, const float* __restrict__ cnt,
                            const float* __restrict__ x,
                            const float* __restrict__ wl, const float* __restrict__ bl,
                            const float* __restrict__ wr,
                            float* __restrict__ out, int n_nodes) {
    constexpr int NT  = 32;
    constexpr int G   = 256 / FOUT;   // node groups
    constexpr int NPT = NT / G;       // nodes per thread
    __shared__ float s_wl[FOUT][33];
    __shared__ float s_wr[FOUT][33];
    __shared__ float s_a[NT][33];     // mean tile
    __shared__ float s_b[NT][33];     // x tile
    __shared__ float s_inv[NT];

    int tid = threadIdx.x;
    int o   = tid % FOUT;
    int g   = tid / FOUT;
    int nb  = blockIdx.x * NT;

    if (tid < NT) {
        int n = nb + tid;
        float c = (n < n_nodes) ? cnt[n] : 1.f;
        s_inv[tid] = 1.f / fmaxf(c, 1.f);
    }
    __syncthreads();

    float acc[NPT];
#pragma unroll
    for (int j = 0; j < NPT; j++) acc[j] = 0.f;

    for (int kk = 0; kk < FDIM; kk += 32) {
        for (int i = tid; i < FOUT * 32; i += 256) {
            int oo = i >> 5, k = i & 31;
            s_wl[oo][k] = wl[oo * FDIM + kk + k];
            s_wr[oo][k] = wr[oo * FDIM + kk + k];
        }
        for (int i = tid; i < NT * 32; i += 256) {
            int n = i >> 5, k = i & 31;
            int gn = nb + n;
            if (gn < n_nodes) {
                s_a[n][k] = msg[(size_t)gn * FDIM + kk + k] * s_inv[n];
                s_b[n][k] = x[(size_t)gn * FDIM + kk + k];
            } else {
                s_a[n][k] = 0.f;
                s_b[n][k] = 0.f;
            }
        }
        __syncthreads();
#pragma unroll
        for (int k = 0; k < 32; k++) {
            float wlv = s_wl[o][k];
            float wrv = s_wr[o][k];
#pragma unroll
            for (int j = 0; j < NPT; j++) {
                int n = g + j * G;
                acc[j] += s_a[n][k] * wlv + s_b[n][k] * wrv;
            }
        }
        __syncthreads();
    }
    float bo = bl[o];
#pragma unroll
    for (int j = 0; j < NPT; j++) {
        int n = nb + g + j * G;
        if (n < n_nodes) out[(size_t)n * FOUT + o] = fmaxf(acc[j] + bo, 0.f);
    }
}

// ---------------- distance to last reference node (sort key) ----------------
__global__ void lastdist(const float* __restrict__ o1, const float* __restrict__ bref,
                         float* __restrict__ lastd, int n) {
    int i = blockIdx.x * blockDim.x + threadIdx.x;
    if (i >= n) return;
    const float* a = o1 + (size_t)i * 64;
    float dot = 0.f, a2 = 0.f, b2 = 0.f;
#pragma unroll
    for (int k = 0; k < 64; k++) {
        float av = a[k];
        float bv = __ldg(bref + k);
        dot += av * bv;
        a2  += av * av;
        b2  += bv * bv;
    }
    lastd[i] = sqrtf(fmaxf(a2 + b2 - 2.f * dot, 0.f));
}

// ---------------- exact stable top-50 per graph via rank counting ----------------
__global__ void topk_kernel(const float* __restrict__ lastd, int* __restrict__ topk) {
    __shared__ float s_v[NPG];
    int b = blockIdx.x;
    for (int i = threadIdx.x; i < NPG; i += 256) s_v[i] = lastd[b * NPG + i];
    __syncthreads();
    int cand = blockIdx.y * 256 + threadIdx.x;
    if (cand < NPG) {
        float v = s_v[cand];
        int rank = 0;
        for (int j = 0; j < NPG; j++) {
            float u = s_v[j];
            rank += (u > v) || (u == v && j < cand);
        }
        if (rank < KSEL) topk[b * KSEL + rank] = b * NPG + cand;
    }
}

// ---------------- gather 199 distances for each selected row ----------------
__global__ void featgather(const int* __restrict__ topk, const float* __restrict__ o1,
                           const float* __restrict__ o2, float* __restrict__ feat) {
    int idx = blockIdx.x;               // 0..499  (= b*KSEL + rank)
    int row = topk[idx];
    __shared__ float s_a[64];
    __shared__ float s_a2;
    int t = threadIdx.x;
    if (t < 64) s_a[t] = o1[(size_t)row * 64 + t];
    __syncthreads();
    if (t == 0) {
        float s = 0.f;
        for (int k = 0; k < 64; k++) s += s_a[k] * s_a[k];
        s_a2 = s;
    }
    __syncthreads();
    if (t < N2) {
        const float* br = o2 + (size_t)t * 64;
        float dot = 0.f, b2 = 0.f;
#pragma unroll
        for (int k = 0; k < 64; k++) {
            float bv = br[k];
            dot += s_a[k] * bv;
            b2  += bv * bv;
        }
        float d2 = s_a2 + b2 - 2.f * dot;
        feat[idx * N2 + t] = sqrtf(fmaxf(d2, 0.f));
    }
}

// ---------------- fc1: 1280 blocks, each one (b, o) dot over 9950 ----------------
__global__ void fc1_kernel(const float* __restrict__ feat, const float* __restrict__ w,
                           const float* __restrict__ bias, float* __restrict__ z) {
    int b = blockIdx.x >> 7;
    int o = blockIdx.x & 127;
    const float* f  = feat + (size_t)b * NFEAT;
    const float* wr = w + (size_t)o * NFEAT;
    float acc = 0.f;
    for (int k = threadIdx.x; k < NFEAT; k += 256) acc += f[k] * wr[k];
    __shared__ float s[256];
    s[threadIdx.x] = acc;
    __syncthreads();
    for (int st = 128; st > 0; st >>= 1) {
        if (threadIdx.x < st) s[threadIdx.x] += s[threadIdx.x + st];
        __syncthreads();
    }
    if (threadIdx.x == 0) z[b * 128 + o] = s[0] + bias[o];
}

// ---------------- LN + relu + fc2 + LN + relu + fc3 + sigmoid ----------------
__global__ void mlp_tail(const float* __restrict__ z1raw,
                         const float* __restrict__ ln1g, const float* __restrict__ ln1b,
                         const float* __restrict__ fc2w, const float* __restrict__ fc2b,
                         const float* __restrict__ ln2g, const float* __restrict__ ln2b,
                         const float* __restrict__ fc3w, const float* __restrict__ fc3b,
                         float* __restrict__ out) {
    int b = blockIdx.x, t = threadIdx.x;
    __shared__ float s_z[128], s_red[128];

    float v = z1raw[b * 128 + t];
    s_red[t] = v;
    __syncthreads();
    for (int st = 64; st > 0; st >>= 1) { if (t < st) s_red[t] += s_red[t + st]; __syncthreads(); }
    float mu = s_red[0] / 128.f;
    __syncthreads();
    float d = v - mu;
    s_red[t] = d * d;
    __syncthreads();
    for (int st = 64; st > 0; st >>= 1) { if (t < st) s_red[t] += s_red[t + st]; __syncthreads(); }
    float var = s_red[0] / 128.f;
    __syncthreads();
    s_z[t] = fmaxf(d * rsqrtf(var + 1e-5f) * ln1g[t] + ln1b[t], 0.f);
    __syncthreads();

    float z2v = 0.f;
    if (t < 64) {
        float a = fc2b[t];
        for (int k = 0; k < 128; k++) a += s_z[k] * fc2w[t * 128 + k];
        z2v = a;
    }
    s_red[t] = (t < 64) ? z2v : 0.f;
    __syncthreads();
    for (int st = 64; st > 0; st >>= 1) { if (t < st) s_red[t] += s_red[t + st]; __syncthreads(); }
    float mu2 = s_red[0] / 64.f;
    __syncthreads();
    float d2 = (t < 64) ? (z2v - mu2) : 0.f;
    s_red[t] = d2 * d2;
    __syncthreads();
    for (int st = 64; st > 0; st >>= 1) { if (t < st) s_red[t] += s_red[t + st]; __syncthreads(); }
    float var2 = s_red[0] / 64.f;
    __syncthreads();
    float z2n = 0.f;
    if (t < 64) z2n = fmaxf(d2 * rsqrtf(var2 + 1e-5f) * ln2g[t] + ln2b[t], 0.f);
    s_red[t] = (t < 64) ? z2n * fc3w[t] : 0.f;
    __syncthreads();
    for (int st = 64; st > 0; st >>= 1) { if (t < st) s_red[t] += s_red[t + st]; __syncthreads(); }
    if (t == 0) out[b] = 1.f / (1.f + expf(-(s_red[0] + fc3b[0])));
}

// ---------------- launch ----------------
static inline int gr(int n) { return (n + 255) / 256; }

extern "C" void kernel_launch(void* const* d_in, const int* in_sizes, int n_in,
                              void* d_out, int out_size) {
    const float* x1   = (const float*)d_in[0];
    const int*   ei1  = (const int*)  d_in[1];
    const float* x2   = (const float*)d_in[3];
    const int*   ei2  = (const int*)  d_in[4];
    const float* w1l  = (const float*)d_in[5];
    const float* b1l  = (const float*)d_in[6];
    const float* w1r  = (const float*)d_in[7];
    const float* w2l  = (const float*)d_in[8];
    const float* b2l  = (const float*)d_in[9];
    const float* w2r  = (const float*)d_in[10];
    const float* fc1w = (const float*)d_in[11];
    const float* fc1b = (const float*)d_in[12];
    const float* ln1g = (const float*)d_in[13];
    const float* ln1b = (const float*)d_in[14];
    const float* fc2w = (const float*)d_in[15];
    const float* fc2b = (const float*)d_in[16];
    const float* ln2g = (const float*)d_in[17];
    const float* ln2b = (const float*)d_in[18];
    const float* fc3w = (const float*)d_in[19];
    const float* fc3b = (const float*)d_in[20];
    float* out = (float*)d_out;

    const int E1 = in_sizes[1] / 2;
    const int E2 = in_sizes[4] / 2;

    float *msg1, *h1, *o1, *cnt1, *msg2, *h2, *o2, *cnt2, *lastd, *featp, *z1raw;
    int* topkp;
    cudaGetSymbolAddress((void**)&msg1, g_msg1);
    cudaGetSymbolAddress((void**)&h1,   g_h1);
    cudaGetSymbolAddress((void**)&o1,   g_o1);
    cudaGetSymbolAddress((void**)&cnt1, g_cnt1);
    cudaGetSymbolAddress((void**)&msg2, g_msg2);
    cudaGetSymbolAddress((void**)&h2,   g_h2);
    cudaGetSymbolAddress((void**)&o2,   g_o2);
    cudaGetSymbolAddress((void**)&cnt2, g_cnt2);
    cudaGetSymbolAddress((void**)&lastd, g_lastd);
    cudaGetSymbolAddress((void**)&topkp, g_topk);
    cudaGetSymbolAddress((void**)&featp, g_feat);
    cudaGetSymbolAddress((void**)&z1raw, g_z1raw);

    // ---- degree counts + layer-1 aggregation ----
    zerok<<<gr(N1), 256>>>(cnt1, N1);
    zerok<<<gr(N1 * FDIM), 256>>>(msg1, N1 * FDIM);
    zerok<<<gr(N2), 256>>>(cnt2, N2);
    zerok<<<gr(N2 * FDIM), 256>>>(msg2, N2 * FDIM);
    countk<<<gr(E1), 256>>>(ei1 + E1, E1, cnt1);
    countk<<<gr(E2), 256>>>(ei2 + E2, E2, cnt2);
    scatterk<<<gr(E1 * 32), 256>>>(x1, ei1, ei1 + E1, E1, msg1);
    scatterk<<<gr(E2 * 32), 256>>>(x2, ei2, ei2 + E2, E2, msg2);

    // ---- layer 1 linear ----
    sage_linear<128><<<(N1 + 31) / 32, 256>>>(msg1, cnt1, x1, w1l, b1l, w1r, h1, N1);
    sage_linear<128><<<(N2 + 31) / 32, 256>>>(msg2, cnt2, x2, w1l, b1l, w1r, h2, N2);

    // ---- layer-2 aggregation + linear ----
    zerok<<<gr(N1 * FDIM), 256>>>(msg1, N1 * FDIM);
    zerok<<<gr(N2 * FDIM), 256>>>(msg2, N2 * FDIM);
    scatterk<<<gr(E1 * 32), 256>>>(h1, ei1, ei1 + E1, E1, msg1);
    scatterk<<<gr(E2 * 32), 256>>>(h2, ei2, ei2 + E2, E2, msg2);
    sage_linear<64><<<(N1 + 31) / 32, 256>>>(msg1, cnt1, h1, w2l, b2l, w2r, o1, N1);
    sage_linear<64><<<(N2 + 31) / 32, 256>>>(msg2, cnt2, h2, w2l, b2l, w2r, o2, N2);

    // ---- sort key, exact stable top-50, selected distances ----
    lastdist<<<gr(N1), 256>>>(o1, o2 + (size_t)(N2 - 1) * 64, lastd, N1);
    topk_kernel<<<dim3(BGR, (NPG + 255) / 256), 256>>>(lastd, topkp);
    featgather<<<BGR * KSEL, 256>>>(topkp, o1, o2, featp);

    // ---- MLP head ----
    fc1_kernel<<<BGR * 128, 256>>>(featp, fc1w, fc1b, z1raw);
    mlp_tail<<<BGR, 128>>>(z1raw, ln1g, ln1b, fc2w, fc2b, ln2g, ln2b, fc3w, fc3b, out);
}

// round 4
// speedup vs baseline: 2.1211x; 2.1211x over previous
#include <cuda_runtime.h>
#include <cuda_bf16.h>
#include <math.h>

#define N1 50000
#define N2 199
#define FDIM 128
#define BGR 10
#define NPG 5000
#define KSEL 50
#define NFEAT (KSEL * N2)   // 9950
#define E1MAX 1000000
#define E2MAX 4000

// ---------------- scratch (device globals; no allocation) ----------------
__device__ float g_msg1[N1 * FDIM];
__device__ float g_h1  [N1 * FDIM];
__device__ float g_o1  [N1 * 64];
__device__ float g_msg2[N2 * FDIM];
__device__ float g_h2  [N2 * FDIM];
__device__ float g_o2  [N2 * 64];
__device__ int   g_off1[N1 + 1];
__device__ int   g_cur1[N1];
__device__ int   g_el1 [E1MAX];
__device__ int   g_off2[N2 + 1];
__device__ int   g_cur2[N2];
__device__ int   g_el2 [E2MAX];
__device__ float g_lastd[N1];
__device__ int   g_topk[BGR * KSEL];
__device__ float g_feat[BGR * NFEAT];
__device__ float g_z1raw[BGR * 128];

// ---------------- CSR build ----------------
__global__ void zeroik(int* p, int n) {
    int i = blockIdx.x * blockDim.x + threadIdx.x;
    if (i < n) p[i] = 0;
}

__global__ void cntk(const int* __restrict__ dst, int e, int* __restrict__ cur) {
    int i = blockIdx.x * blockDim.x + threadIdx.x;
    if (i < e) atomicAdd(&cur[dst[i]], 1);
}

// single-block inclusive scan -> offsets; resets cur to 0 for fill pass
__global__ void scank(int* __restrict__ cur, int* __restrict__ off, int n) {
    __shared__ int s[1024];
    __shared__ int carry;
    int tid = threadIdx.x;
    if (tid == 0) { carry = 0; off[0] = 0; }
    __syncthreads();
    for (int base = 0; base < n; base += 1024) {
        int i = base + tid;
        int v = (i < n) ? cur[i] : 0;
        s[tid] = v;
        __syncthreads();
        for (int d = 1; d < 1024; d <<= 1) {
            int t = (tid >= d) ? s[tid - d] : 0;
            __syncthreads();
            s[tid] += t;
            __syncthreads();
        }
        if (i < n) { off[i + 1] = carry + s[tid]; cur[i] = 0; }
        __syncthreads();
        if (tid == 0) carry += s[1023];
        __syncthreads();
    }
}

__global__ void fillk(const int* __restrict__ src, const int* __restrict__ dst, int e,
                      const int* __restrict__ off, int* __restrict__ cur,
                      int* __restrict__ el) {
    int i = blockIdx.x * blockDim.x + threadIdx.x;
    if (i < e) {
        int d = dst[i];
        int p = atomicAdd(&cur[d], 1);
        el[off[d] + p] = src[i];
    }
}

// ---------------- gather: mean of neighbor features (one warp per node) ----------------
__global__ void gather_mean(const float* __restrict__ x, const int* __restrict__ off,
                            const int* __restrict__ el, int n, float* __restrict__ msg) {
    int w = (blockIdx.x * blockDim.x + threadIdx.x) >> 5;
    if (w >= n) return;
    int c = (threadIdx.x & 31) * 4;
    int beg = off[w], end = off[w + 1];
    float ax = 0.f, ay = 0.f, az = 0.f, aw = 0.f;
    for (int j = beg; j < end; j++) {
        int s = __ldg(el + j);
        float4 v = *reinterpret_cast<const float4*>(x + (size_t)s * FDIM + c);
        ax += v.x; ay += v.y; az += v.z; aw += v.w;
    }
    float inv = 1.f / fmaxf((float)(end - beg), 1.f);
    float4 r = make_float4(ax * inv, ay * inv, az * inv, aw * inv);
    *reinterpret_cast<float4*>(msg + (size_t)w * FDIM + c) = r;
}

// ---------------- SAGE linear: out = relu(mean @ wl^T + bl + x @ wr^T) ----------------
// Register-blocked: 4 outputs x NPT nodes per thread, LDS.128 vector loads.
template <int FOUT>
__global__ __launch_bounds__(256)
void sage_linear2(const float* __restrict__ mean, const float* __restrict__ x,
                  const float* __restrict__ wl, const float* __restrict__ bl,
                  const float* __restrict__ wr,
                  float* __restrict__ out, int n_nodes) {
    constexpr int NT  = 64;
    constexpr int OPT = 4;
    constexpr int OG  = FOUT / OPT;     // 32 (FOUT=128) or 16 (FOUT=64)
    constexpr int NG  = 256 / OG;       // 8 or 16
    constexpr int NPT = NT / NG;        // 8 or 4
    constexpr int WS  = FOUT + 4;
    constexpr int XS  = NT + 4;

    __shared__ __align__(16) float s_wl[32][WS];
    __shared__ __align__(16) float s_wr[32][WS];
    __shared__ __align__(16) float s_a[32][XS];
    __shared__ __align__(16) float s_b[32][XS];

    int tid = threadIdx.x;
    int og  = tid % OG;
    int ng  = tid / OG;
    int nb  = blockIdx.x * NT;

    float acc[OPT][NPT];
#pragma unroll
    for (int oi = 0; oi < OPT; oi++)
#pragma unroll
        for (int j = 0; j < NPT; j++) acc[oi][j] = 0.f;

    for (int kk = 0; kk < FDIM; kk += 32) {
        for (int i = tid; i < FOUT * 32; i += 256) {
            int o = i >> 5, k = i & 31;
            s_wl[k][o] = wl[o * FDIM + kk + k];
            s_wr[k][o] = wr[o * FDIM + kk + k];
        }
        for (int i = tid; i < NT * 32; i += 256) {
            int n = i >> 5, k = i & 31;
            int gn = nb + n;
            float av = 0.f, bv = 0.f;
            if (gn < n_nodes) {
                av = mean[(size_t)gn * FDIM + kk + k];
                bv = x[(size_t)gn * FDIM + kk + k];
            }
            s_a[k][n] = av;
            s_b[k][n] = bv;
        }
        __syncthreads();
#pragma unroll
        for (int k = 0; k < 32; k++) {
            float4 wl4 = *reinterpret_cast<const float4*>(&s_wl[k][og * OPT]);
            float4 wr4 = *reinterpret_cast<const float4*>(&s_wr[k][og * OPT]);
            float wlv[4] = {wl4.x, wl4.y, wl4.z, wl4.w};
            float wrv[4] = {wr4.x, wr4.y, wr4.z, wr4.w};
#pragma unroll
            for (int j0 = 0; j0 < NPT; j0 += 4) {
                float4 a4 = *reinterpret_cast<const float4*>(&s_a[k][ng * NPT + j0]);
                float4 b4 = *reinterpret_cast<const float4*>(&s_b[k][ng * NPT + j0]);
                float aa[4] = {a4.x, a4.y, a4.z, a4.w};
                float bb[4] = {b4.x, b4.y, b4.z, b4.w};
#pragma unroll
                for (int oi = 0; oi < OPT; oi++)
#pragma unroll
                    for (int j = 0; j < 4; j++)
                        acc[oi][j0 + j] += aa[j] * wlv[oi] + bb[j] * wrv[oi];
            }
        }
        __syncthreads();
    }

#pragma unroll
    for (int j = 0; j < NPT; j++) {
        int n = nb + ng * NPT + j;
        if (n < n_nodes) {
#pragma unroll
            for (int oi = 0; oi < OPT; oi++) {
                int o = og * OPT + oi;
                out[(size_t)n * FOUT + o] = fmaxf(acc[oi][j] + bl[o], 0.f);
            }
        }
    }
}

// ---------------- distance to last reference node (sort key) ----------------
__global__ void lastdist(const float* __restrict__ o1, const float* __restrict__ bref,
                         float* __restrict__ lastd, int n) {
    int i = blockIdx.x * blockDim.x + threadIdx.x;
    if (i >= n) return;
    const float* a = o1 + (size_t)i * 64;
    float dot = 0.f, a2 = 0.f, b2 = 0.f;
#pragma unroll
    for (int k = 0; k < 64; k++) {
        float av = a[k];
        float bv = __ldg(bref + k);
        dot += av * bv;
        a2  += av * av;
        b2  += bv * bv;
    }
    lastd[i] = sqrtf(fmaxf(a2 + b2 - 2.f * dot, 0.f));
}

// ---------------- exact stable top-50 per graph via rank counting ----------------
__global__ void topk_kernel(const float* __restrict__ lastd, int* __restrict__ topk) {
    __shared__ float s_v[NPG];
    int b = blockIdx.x;
    for (int i = threadIdx.x; i < NPG; i += 256) s_v[i] = lastd[b * NPG + i];
    __syncthreads();
    int cand = blockIdx.y * 256 + threadIdx.x;
    if (cand < NPG) {
        float v = s_v[cand];
        int rank = 0;
        for (int j = 0; j < NPG; j++) {
            float u = s_v[j];
            rank += (u > v) || (u == v && j < cand);
        }
        if (rank < KSEL) topk[b * KSEL + rank] = b * NPG + cand;
    }
}

// ---------------- gather 199 distances for each selected row ----------------
__global__ void featgather(const int* __restrict__ topk, const float* __restrict__ o1,
                           const float* __restrict__ o2, float* __restrict__ feat) {
    int idx = blockIdx.x;               // 0..499  (= b*KSEL + rank)
    int row = topk[idx];
    __shared__ float s_a[64];
    __shared__ float s_a2;
    int t = threadIdx.x;
    if (t < 64) s_a[t] = o1[(size_t)row * 64 + t];
    __syncthreads();
    if (t == 0) {
        float s = 0.f;
        for (int k = 0; k < 64; k++) s += s_a[k] * s_a[k];
        s_a2 = s;
    }
    __syncthreads();
    if (t < N2) {
        const float* br = o2 + (size_t)t * 64;
        float dot = 0.f, b2 = 0.f;
#pragma unroll
        for (int k = 0; k < 64; k++) {
            float bv = br[k];
            dot += s_a[k] * bv;
            b2  += bv * bv;
        }
        float d2 = s_a2 + b2 - 2.f * dot;
        feat[idx * N2 + t] = sqrtf(fmaxf(d2, 0.f));
    }
}

// ---------------- fc1: 1280 blocks, each one (b, o) dot over 9950 ----------------
__global__ void fc1_kernel(const float* __restrict__ feat, const float* __restrict__ w,
                           const float* __restrict__ bias, float* __restrict__ z) {
    int b = blockIdx.x >> 7;
    int o = blockIdx.x & 127;
    const float* f  = feat + (size_t)b * NFEAT;
    const float* wr = w + (size_t)o * NFEAT;
    float acc = 0.f;
    for (int k = threadIdx.x; k < NFEAT; k += 256) acc += f[k] * wr[k];
    __shared__ float s[256];
    s[threadIdx.x] = acc;
    __syncthreads();
    for (int st = 128; st > 0; st >>= 1) {
        if (threadIdx.x < st) s[threadIdx.x] += s[threadIdx.x + st];
        __syncthreads();
    }
    if (threadIdx.x == 0) z[b * 128 + o] = s[0] + bias[o];
}

// ---------------- LN + relu + fc2 + LN + relu + fc3 + sigmoid ----------------
__global__ void mlp_tail(const float* __restrict__ z1raw,
                         const float* __restrict__ ln1g, const float* __restrict__ ln1b,
                         const float* __restrict__ fc2w, const float* __restrict__ fc2b,
                         const float* __restrict__ ln2g, const float* __restrict__ ln2b,
                         const float* __restrict__ fc3w, const float* __restrict__ fc3b,
                         float* __restrict__ out) {
    int b = blockIdx.x, t = threadIdx.x;
    __shared__ float s_z[128], s_red[128];

    float v = z1raw[b * 128 + t];
    s_red[t] = v;
    __syncthreads();
    for (int st = 64; st > 0; st >>= 1) { if (t < st) s_red[t] += s_red[t + st]; __syncthreads(); }
    float mu = s_red[0] / 128.f;
    __syncthreads();
    float d = v - mu;
    s_red[t] = d * d;
    __syncthreads();
    for (int st = 64; st > 0; st >>= 1) { if (t < st) s_red[t] += s_red[t + st]; __syncthreads(); }
    float var = s_red[0] / 128.f;
    __syncthreads();
    s_z[t] = fmaxf(d * rsqrtf(var + 1e-5f) * ln1g[t] + ln1b[t], 0.f);
    __syncthreads();

    float z2v = 0.f;
    if (t < 64) {
        float a = fc2b[t];
        for (int k = 0; k < 128; k++) a += s_z[k] * fc2w[t * 128 + k];
        z2v = a;
    }
    s_red[t] = (t < 64) ? z2v : 0.f;
    __syncthreads();
    for (int st = 64; st > 0; st >>= 1) { if (t < st) s_red[t] += s_red[t + st]; __syncthreads(); }
    float mu2 = s_red[0] / 64.f;
    __syncthreads();
    float d2 = (t < 64) ? (z2v - mu2) : 0.f;
    s_red[t] = d2 * d2;
    __syncthreads();
    for (int st = 64; st > 0; st >>= 1) { if (t < st) s_red[t] += s_red[t + st]; __syncthreads(); }
    float var2 = s_red[0] / 64.f;
    __syncthreads();
    float z2n = 0.f;
    if (t < 64) z2n = fmaxf(d2 * rsqrtf(var2 + 1e-5f) * ln2g[t] + ln2b[t], 0.f);
    s_red[t] = (t < 64) ? z2n * fc3w[t] : 0.f;
    __syncthreads();
    for (int st = 64; st > 0; st >>= 1) { if (t < st) s_red[t] += s_red[t + st]; __syncthreads(); }
    if (t == 0) out[b] = 1.f / (1.f + expf(-(s_red[0] + fc3b[0])));
}

// ---------------- launch ----------------
static inline int gr(int n) { return (n + 255) / 256; }

extern "C" void kernel_launch(void* const* d_in, const int* in_sizes, int n_in,
                              void* d_out, int out_size) {
    const float* x1   = (const float*)d_in[0];
    const int*   ei1  = (const int*)  d_in[1];
    const float* x2   = (const float*)d_in[3];
    const int*   ei2  = (const int*)  d_in[4];
    const float* w1l  = (const float*)d_in[5];
    const float* b1l  = (const float*)d_in[6];
    const float* w1r  = (const float*)d_in[7];
    const float* w2l  = (const float*)d_in[8];
    const float* b2l  = (const float*)d_in[9];
    const float* w2r  = (const float*)d_in[10];
    const float* fc1w = (const float*)d_in[11];
    const float* fc1b = (const float*)d_in[12];
    const float* ln1g = (const float*)d_in[13];
    const float* ln1b = (const float*)d_in[14];
    const float* fc2w = (const float*)d_in[15];
    const float* fc2b = (const float*)d_in[16];
    const float* ln2g = (const float*)d_in[17];
    const float* ln2b = (const float*)d_in[18];
    const float* fc3w = (const float*)d_in[19];
    const float* fc3b = (const float*)d_in[20];
    float* out = (float*)d_out;

    const int E1 = in_sizes[1] / 2;
    const int E2 = in_sizes[4] / 2;

    float *msg1, *h1, *o1, *msg2, *h2, *o2, *lastd, *featp, *z1raw;
    int *off1, *cur1, *el1, *off2, *cur2, *el2, *topkp;
    cudaGetSymbolAddress((void**)&msg1, g_msg1);
    cudaGetSymbolAddress((void**)&h1,   g_h1);
    cudaGetSymbolAddress((void**)&o1,   g_o1);
    cudaGetSymbolAddress((void**)&msg2, g_msg2);
    cudaGetSymbolAddress((void**)&h2,   g_h2);
    cudaGetSymbolAddress((void**)&o2,   g_o2);
    cudaGetSymbolAddress((void**)&off1, g_off1);
    cudaGetSymbolAddress((void**)&cur1, g_cur1);
    cudaGetSymbolAddress((void**)&el1,  g_el1);
    cudaGetSymbolAddress((void**)&off2, g_off2);
    cudaGetSymbolAddress((void**)&cur2, g_cur2);
    cudaGetSymbolAddress((void**)&el2,  g_el2);
    cudaGetSymbolAddress((void**)&lastd, g_lastd);
    cudaGetSymbolAddress((void**)&topkp, g_topk);
    cudaGetSymbolAddress((void**)&featp, g_feat);
    cudaGetSymbolAddress((void**)&z1raw, g_z1raw);

    // ---- CSR build (both graphs) ----
    zeroik<<<gr(N1), 256>>>(cur1, N1);
    zeroik<<<gr(N2), 256>>>(cur2, N2);
    cntk<<<gr(E1), 256>>>(ei1 + E1, E1, cur1);
    cntk<<<gr(E2), 256>>>(ei2 + E2, E2, cur2);
    scank<<<1, 1024>>>(cur1, off1, N1);
    scank<<<1, 1024>>>(cur2, off2, N2);
    fillk<<<gr(E1), 256>>>(ei1, ei1 + E1, E1, off1, cur1, el1);
    fillk<<<gr(E2), 256>>>(ei2, ei2 + E2, E2, off2, cur2, el2);

    // ---- layer 1: gather mean + linear ----
    gather_mean<<<gr(N1 * 32), 256>>>(x1, off1, el1, N1, msg1);
    gather_mean<<<gr(N2 * 32), 256>>>(x2, off2, el2, N2, msg2);
    sage_linear2<128><<<(N1 + 63) / 64, 256>>>(msg1, x1, w1l, b1l, w1r, h1, N1);
    sage_linear2<128><<<(N2 + 63) / 64, 256>>>(msg2, x2, w1l, b1l, w1r, h2, N2);

    // ---- layer 2: gather mean + linear ----
    gather_mean<<<gr(N1 * 32), 256>>>(h1, off1, el1, N1, msg1);
    gather_mean<<<gr(N2 * 32), 256>>>(h2, off2, el2, N2, msg2);
    sage_linear2<64><<<(N1 + 63) / 64, 256>>>(msg1, h1, w2l, b2l, w2r, o1, N1);
    sage_linear2<64><<<(N2 + 63) / 64, 256>>>(msg2, h2, w2l, b2l, w2r, o2, N2);

    // ---- sort key, exact stable top-50, selected distances ----
    lastdist<<<gr(N1), 256>>>(o1, o2 + (size_t)(N2 - 1) * 64, lastd, N1);
    topk_kernel<<<dim3(BGR, (NPG + 255) / 256), 256>>>(lastd, topkp);
    featgather<<<BGR * KSEL, 256>>>(topkp, o1, o2, featp);

    // ---- MLP head ----
    fc1_kernel<<<BGR * 128, 256>>>(featp, fc1w, fc1b, z1raw);
    mlp_tail<<<BGR, 128>>>(z1raw, ln1g, ln1b, fc2w, fc2b, ln2g, ln2b, fc3w, fc3b, out);
}

// round 5
// speedup vs baseline: 2.9970x; 1.4130x over previous
#include <cuda_runtime.h>
#include <cuda_bf16.h>
#include <math.h>

#define N1 50000
#define N2 199
#define FDIM 128
#define BGR 10
#define NPG 5000
#define KSEL 50
#define NFEAT (KSEL * N2)   // 9950
#define E1MAX 1000000
#define E2MAX 4000
#define G1B   ((N1 + 63) / 64)   // 782 blocks for 64-node tiles
#define G2B   ((N2 + 63) / 64)   // 4

// ---------------- scratch (device globals; no allocation) ----------------
__device__ float g_msg1[N1 * FDIM];   // layer1: mean(x) ; layer2: pp = h@[w2l|w2r]^T
__device__ float g_h1  [N1 * FDIM];
__device__ float g_o1  [N1 * 64];
__device__ float g_msg2[N2 * FDIM];
__device__ float g_h2  [N2 * FDIM];
__device__ float g_o2  [N2 * 64];
__device__ int   g_off1[N1 + 1];
__device__ int   g_cur1[N1];
__device__ int   g_el1 [E1MAX];
__device__ int   g_off2[N2 + 1];
__device__ int   g_cur2[N2];
__device__ int   g_el2 [E2MAX];
__device__ int   g_bsum[256];
__device__ float g_lastd[N1];
__device__ int   g_topk[BGR * KSEL];
__device__ float g_feat[BGR * NFEAT];
__device__ float g_z1raw[BGR * 128];

// ---------------- CSR build (merged for both graphs) ----------------
__global__ void zero2(int* a, int na, int* b, int nb_) {
    int i = blockIdx.x * blockDim.x + threadIdx.x;
    if (i < na) a[i] = 0;
    else if (i < na + nb_) b[i - na] = 0;
}

__global__ void cnt2(const int* __restrict__ d1, int e1, int* __restrict__ c1,
                     const int* __restrict__ d2, int e2, int* __restrict__ c2) {
    int i = blockIdx.x * blockDim.x + threadIdx.x;
    if (i < e1) atomicAdd(&c1[d1[i]], 1);
    else if (i < e1 + e2) atomicAdd(&c2[d2[i - e1]], 1);
}

__global__ void fill2(const int* __restrict__ s1, const int* __restrict__ d1, int e1,
                      const int* __restrict__ off1, int* __restrict__ cur1, int* __restrict__ el1,
                      const int* __restrict__ s2, const int* __restrict__ d2, int e2,
                      const int* __restrict__ off2, int* __restrict__ cur2, int* __restrict__ el2) {
    int i = blockIdx.x * blockDim.x + threadIdx.x;
    if (i < e1) {
        int d = d1[i];
        int p = atomicAdd(&cur1[d], 1);
        el1[off1[d] + p] = s1[i];
    } else if (i < e1 + e2) {
        int j = i - e1;
        int d = d2[j];
        int p = atomicAdd(&cur2[d], 1);
        el2[off2[d] + p] = s2[j];
    }
}

// ---------------- multi-block scan (graph1) ----------------
__global__ void scan_partial(const int* __restrict__ cur, int* __restrict__ off,
                             int* __restrict__ bsum, int n) {
    __shared__ int s[256];
    int tid = threadIdx.x;
    int i = blockIdx.x * 256 + tid;
    s[tid] = (i < n) ? cur[i] : 0;
    __syncthreads();
    for (int d = 1; d < 256; d <<= 1) {
        int t = (tid >= d) ? s[tid - d] : 0;
        __syncthreads();
        s[tid] += t;
        __syncthreads();
    }
    if (i < n) off[i + 1] = s[tid];
    if (tid == 255) bsum[blockIdx.x] = s[255];
}

__global__ void scan_bsum(int* __restrict__ bsum, int nb_) {
    __shared__ int s[256];
    int tid = threadIdx.x;
    s[tid] = (tid < nb_) ? bsum[tid] : 0;
    __syncthreads();
    for (int d = 1; d < 256; d <<= 1) {
        int t = (tid >= d) ? s[tid - d] : 0;
        __syncthreads();
        s[tid] += t;
        __syncthreads();
    }
    if (tid < nb_) bsum[tid] = (tid == 0) ? 0 : s[tid - 1];  // exclusive
}

__global__ void scan_fix(int* __restrict__ off, const int* __restrict__ bsum,
                         int* __restrict__ cur, int n) {
    int i = blockIdx.x * 256 + threadIdx.x;
    if (i < n) { off[i + 1] += bsum[blockIdx.x]; cur[i] = 0; }
    if (i == 0) off[0] = 0;
}

// small single-block scan for graph2
__global__ void scank(int* __restrict__ cur, int* __restrict__ off, int n) {
    __shared__ int s[1024];
    __shared__ int carry;
    int tid = threadIdx.x;
    if (tid == 0) { carry = 0; off[0] = 0; }
    __syncthreads();
    for (int base = 0; base < n; base += 1024) {
        int i = base + tid;
        int v = (i < n) ? cur[i] : 0;
        s[tid] = v;
        __syncthreads();
        for (int d = 1; d < 1024; d <<= 1) {
            int t = (tid >= d) ? s[tid - d] : 0;
            __syncthreads();
            s[tid] += t;
            __syncthreads();
        }
        if (i < n) { off[i + 1] = carry + s[tid]; cur[i] = 0; }
        __syncthreads();
        if (tid == 0) carry += s[1023];
        __syncthreads();
    }
}

// ---------------- layer-1 gather: mean of neighbor raw features (both graphs) ----------------
__global__ void gather_mean2(const float* __restrict__ x1, const int* __restrict__ off1,
                             const int* __restrict__ el1,
                             const float* __restrict__ x2, const int* __restrict__ off2,
                             const int* __restrict__ el2,
                             float* __restrict__ m1, float* __restrict__ m2) {
    int w = (blockIdx.x * blockDim.x + threadIdx.x) >> 5;
    const float* x; const int* off; const int* el; float* msg;
    if (w < N1) { x = x1; off = off1; el = el1; msg = m1; }
    else if (w < N1 + N2) { w -= N1; x = x2; off = off2; el = el2; msg = m2; }
    else return;
    int c = (threadIdx.x & 31) * 4;
    int beg = off[w], end = off[w + 1];
    float ax = 0.f, ay = 0.f, az = 0.f, aw = 0.f;
    for (int j = beg; j < end; j++) {
        int s = __ldg(el + j);
        float4 v = *reinterpret_cast<const float4*>(x + (size_t)s * FDIM + c);
        ax += v.x; ay += v.y; az += v.z; aw += v.w;
    }
    float inv = 1.f / fmaxf((float)(end - beg), 1.f);
    *reinterpret_cast<float4*>(msg + (size_t)w * FDIM + c) =
        make_float4(ax * inv, ay * inv, az * inv, aw * inv);
}

// ---------------- layer-1 linear (both graphs): h = relu(mean@wl^T + bl + x@wr^T) ----------------
__global__ __launch_bounds__(256)
void sage1_merged(const float* __restrict__ m1, const float* __restrict__ x1,
                  float* __restrict__ h1out,
                  const float* __restrict__ m2, const float* __restrict__ x2,
                  float* __restrict__ h2out,
                  const float* __restrict__ wl, const float* __restrict__ bl,
                  const float* __restrict__ wr) {
    // FOUT=128 tile: 64 nodes/block, 4 outs x 8 nodes per thread
    constexpr int NT = 64, OPT = 4, OG = 32, NG = 8, NPT = 8;
    const float *mean, *x; float* out; int n, nb;
    if (blockIdx.x < G1B) { mean = m1; x = x1; out = h1out; n = N1; nb = blockIdx.x * NT; }
    else { mean = m2; x = x2; out = h2out; n = N2; nb = (blockIdx.x - G1B) * NT; }

    __shared__ __align__(16) float s_wl[32][132];
    __shared__ __align__(16) float s_wr[32][132];
    __shared__ __align__(16) float s_a[32][68];
    __shared__ __align__(16) float s_b[32][68];

    int tid = threadIdx.x;
    int og = tid % OG, ng = tid / OG;

    float acc[OPT][NPT];
#pragma unroll
    for (int oi = 0; oi < OPT; oi++)
#pragma unroll
        for (int j = 0; j < NPT; j++) acc[oi][j] = 0.f;

    for (int kk = 0; kk < FDIM; kk += 32) {
        for (int i = tid; i < 128 * 32; i += 256) {
            int o = i >> 5, k = i & 31;
            s_wl[k][o] = wl[o * FDIM + kk + k];
            s_wr[k][o] = wr[o * FDIM + kk + k];
        }
        for (int i = tid; i < NT * 32; i += 256) {
            int nn = i >> 5, k = i & 31;
            int gn = nb + nn;
            float av = 0.f, bv = 0.f;
            if (gn < n) {
                av = mean[(size_t)gn * FDIM + kk + k];
                bv = x[(size_t)gn * FDIM + kk + k];
            }
            s_a[k][nn] = av;
            s_b[k][nn] = bv;
        }
        __syncthreads();
#pragma unroll
        for (int k = 0; k < 32; k++) {
            float4 wl4 = *reinterpret_cast<const float4*>(&s_wl[k][og * OPT]);
            float4 wr4 = *reinterpret_cast<const float4*>(&s_wr[k][og * OPT]);
            float wlv[4] = {wl4.x, wl4.y, wl4.z, wl4.w};
            float wrv[4] = {wr4.x, wr4.y, wr4.z, wr4.w};
#pragma unroll
            for (int j0 = 0; j0 < NPT; j0 += 4) {
                float4 a4 = *reinterpret_cast<const float4*>(&s_a[k][ng * NPT + j0]);
                float4 b4 = *reinterpret_cast<const float4*>(&s_b[k][ng * NPT + j0]);
                float aa[4] = {a4.x, a4.y, a4.z, a4.w};
                float bb[4] = {b4.x, b4.y, b4.z, b4.w};
#pragma unroll
                for (int oi = 0; oi < OPT; oi++)
#pragma unroll
                    for (int j = 0; j < 4; j++)
                        acc[oi][j0 + j] += aa[j] * wlv[oi] + bb[j] * wrv[oi];
            }
        }
        __syncthreads();
    }
#pragma unroll
    for (int j = 0; j < NPT; j++) {
        int nn = nb + ng * NPT + j;
        if (nn < n) {
#pragma unroll
            for (int oi = 0; oi < OPT; oi++) {
                int o = og * OPT + oi;
                out[(size_t)nn * 128 + o] = fmaxf(acc[oi][j] + bl[o], 0.f);
            }
        }
    }
}

// ---------------- layer-2 pre-transform: pp = h @ [w2l | w2r]^T (both graphs) ----------------
__global__ __launch_bounds__(256)
void dual_linear(const float* __restrict__ h1in, float* __restrict__ pp1,
                 const float* __restrict__ h2in, float* __restrict__ pp2,
                 const float* __restrict__ w2l, const float* __restrict__ w2r) {
    constexpr int NT = 64, OPT = 4, OG = 32, NG = 8, NPT = 8;
    const float* h; float* pp; int n, nb;
    if (blockIdx.x < G1B) { h = h1in; pp = pp1; n = N1; nb = blockIdx.x * NT; }
    else { h = h2in; pp = pp2; n = N2; nb = (blockIdx.x - G1B) * NT; }

    __shared__ __align__(16) float s_w[32][132];
    __shared__ __align__(16) float s_b[32][68];

    int tid = threadIdx.x;
    int og = tid % OG, ng = tid / OG;

    float acc[OPT][NPT];
#pragma unroll
    for (int oi = 0; oi < OPT; oi++)
#pragma unroll
        for (int j = 0; j < NPT; j++) acc[oi][j] = 0.f;

    for (int kk = 0; kk < FDIM; kk += 32) {
        for (int i = tid; i < 128 * 32; i += 256) {
            int o = i >> 5, k = i & 31;
            s_w[k][o] = (o < 64) ? w2l[o * FDIM + kk + k] : w2r[(o - 64) * FDIM + kk + k];
        }
        for (int i = tid; i < NT * 32; i += 256) {
            int nn = i >> 5, k = i & 31;
            int gn = nb + nn;
            s_b[k][nn] = (gn < n) ? h[(size_t)gn * FDIM + kk + k] : 0.f;
        }
        __syncthreads();
#pragma unroll
        for (int k = 0; k < 32; k++) {
            float4 w4 = *reinterpret_cast<const float4*>(&s_w[k][og * OPT]);
            float wv[4] = {w4.x, w4.y, w4.z, w4.w};
#pragma unroll
            for (int j0 = 0; j0 < NPT; j0 += 4) {
                float4 b4 = *reinterpret_cast<const float4*>(&s_b[k][ng * NPT + j0]);
                float bb[4] = {b4.x, b4.y, b4.z, b4.w};
#pragma unroll
                for (int oi = 0; oi < OPT; oi++)
#pragma unroll
                    for (int j = 0; j < 4; j++)
                        acc[oi][j0 + j] += bb[j] * wv[oi];
            }
        }
        __syncthreads();
    }
#pragma unroll
    for (int j = 0; j < NPT; j++) {
        int nn = nb + ng * NPT + j;
        if (nn < n) {
#pragma unroll
            for (int oi = 0; oi < OPT; oi++) {
                int o = og * OPT + oi;
                pp[(size_t)nn * 128 + o] = acc[oi][j];
            }
        }
    }
}

// ---------------- layer-2 gather + epilogue (+ optional fused lastdist) ----------------
// o[n] = relu(mean_{s in nbrs}(pp[s][0:64]) + b2l + pp[n][64:128])
__global__ void gather64_final(const float* __restrict__ pp, const int* __restrict__ off,
                               const int* __restrict__ el, const float* __restrict__ b2l,
                               int n, float* __restrict__ outp,
                               const float* __restrict__ bref, float* __restrict__ lastd) {
    int w = (blockIdx.x * blockDim.x + threadIdx.x) >> 5;
    if (w >= n) return;
    int lane = threadIdx.x & 31;
    int c = lane * 2;
    int beg = off[w], end = off[w + 1];
    float a0 = 0.f, a1 = 0.f;
    for (int j = beg; j < end; j++) {
        int s = __ldg(el + j);
        float2 v = *reinterpret_cast<const float2*>(pp + (size_t)s * 128 + c);
        a0 += v.x; a1 += v.y;
    }
    float inv = 1.f / fmaxf((float)(end - beg), 1.f);
    float2 r  = *reinterpret_cast<const float2*>(pp + (size_t)w * 128 + 64 + c);
    float2 bb = *reinterpret_cast<const float2*>(b2l + c);
    float o0 = fmaxf(a0 * inv + bb.x + r.x, 0.f);
    float o1 = fmaxf(a1 * inv + bb.y + r.y, 0.f);
    *reinterpret_cast<float2*>(outp + (size_t)w * 64 + c) = make_float2(o0, o1);
    if (lastd) {
        float2 bv = *reinterpret_cast<const float2*>(bref + c);
        float acc = o0 * o0 + o1 * o1 + bv.x * bv.x + bv.y * bv.y
                  - 2.f * (o0 * bv.x + o1 * bv.y);
#pragma unroll
        for (int m = 16; m >= 1; m >>= 1) acc += __shfl_xor_sync(0xffffffffu, acc, m);
        if (lane == 0) lastd[w] = sqrtf(fmaxf(acc, 0.f));
    }
}

// ---------------- exact stable top-50 per graph via rank counting ----------------
__global__ void topk_kernel(const float* __restrict__ lastd, int* __restrict__ topk) {
    __shared__ float s_v[NPG];
    int b = blockIdx.x;
    for (int i = threadIdx.x; i < NPG; i += 256) s_v[i] = lastd[b * NPG + i];
    __syncthreads();
    int cand = blockIdx.y * 256 + threadIdx.x;
    if (cand < NPG) {
        float v = s_v[cand];
        int rank = 0;
        for (int j = 0; j < NPG; j++) {
            float u = s_v[j];
            rank += (u > v) || (u == v && j < cand);
        }
        if (rank < KSEL) topk[b * KSEL + rank] = b * NPG + cand;
    }
}

// ---------------- gather 199 distances for each selected row ----------------
__global__ void featgather(const int* __restrict__ topk, const float* __restrict__ o1,
                           const float* __restrict__ o2, float* __restrict__ feat) {
    int idx = blockIdx.x;               // 0..499  (= b*KSEL + rank)
    int row = topk[idx];
    __shared__ float s_a[64];
    __shared__ float s_a2;
    int t = threadIdx.x;
    if (t < 64) s_a[t] = o1[(size_t)row * 64 + t];
    __syncthreads();
    if (t == 0) {
        float s = 0.f;
        for (int k = 0; k < 64; k++) s += s_a[k] * s_a[k];
        s_a2 = s;
    }
    __syncthreads();
    if (t < N2) {
        const float* br = o2 + (size_t)t * 64;
        float dot = 0.f, b2 = 0.f;
#pragma unroll
        for (int k = 0; k < 64; k++) {
            float bv = br[k];
            dot += s_a[k] * bv;
            b2  += bv * bv;
        }
        float d2 = s_a2 + b2 - 2.f * dot;
        feat[idx * N2 + t] = sqrtf(fmaxf(d2, 0.f));
    }
}

// ---------------- fc1: 1280 blocks, each one (b, o) dot over 9950 ----------------
__global__ void fc1_kernel(const float* __restrict__ feat, const float* __restrict__ w,
                           const float* __restrict__ bias, float* __restrict__ z) {
    int b = blockIdx.x >> 7;
    int o = blockIdx.x & 127;
    const float* f  = feat + (size_t)b * NFEAT;
    const float* wr = w + (size_t)o * NFEAT;
    float acc = 0.f;
    for (int k = threadIdx.x; k < NFEAT; k += 256) acc += f[k] * wr[k];
    __shared__ float s[256];
    s[threadIdx.x] = acc;
    __syncthreads();
    for (int st = 128; st > 0; st >>= 1) {
        if (threadIdx.x < st) s[threadIdx.x] += s[threadIdx.x + st];
        __syncthreads();
    }
    if (threadIdx.x == 0) z[b * 128 + o] = s[0] + bias[o];
}

// ---------------- LN + relu + fc2 + LN + relu + fc3 + sigmoid ----------------
__global__ void mlp_tail(const float* __restrict__ z1raw,
                         const float* __restrict__ ln1g, const float* __restrict__ ln1b,
                         const float* __restrict__ fc2w, const float* __restrict__ fc2b,
                         const float* __restrict__ ln2g, const float* __restrict__ ln2b,
                         const float* __restrict__ fc3w, const float* __restrict__ fc3b,
                         float* __restrict__ out) {
    int b = blockIdx.x, t = threadIdx.x;
    __shared__ float s_z[128], s_red[128];

    float v = z1raw[b * 128 + t];
    s_red[t] = v;
    __syncthreads();
    for (int st = 64; st > 0; st >>= 1) { if (t < st) s_red[t] += s_red[t + st]; __syncthreads(); }
    float mu = s_red[0] / 128.f;
    __syncthreads();
    float d = v - mu;
    s_red[t] = d * d;
    __syncthreads();
    for (int st = 64; st > 0; st >>= 1) { if (t < st) s_red[t] += s_red[t + st]; __syncthreads(); }
    float var = s_red[0] / 128.f;
    __syncthreads();
    s_z[t] = fmaxf(d * rsqrtf(var + 1e-5f) * ln1g[t] + ln1b[t], 0.f);
    __syncthreads();

    float z2v = 0.f;
    if (t < 64) {
        float a = fc2b[t];
        for (int k = 0; k < 128; k++) a += s_z[k] * fc2w[t * 128 + k];
        z2v = a;
    }
    s_red[t] = (t < 64) ? z2v : 0.f;
    __syncthreads();
    for (int st = 64; st > 0; st >>= 1) { if (t < st) s_red[t] += s_red[t + st]; __syncthreads(); }
    float mu2 = s_red[0] / 64.f;
    __syncthreads();
    float d2 = (t < 64) ? (z2v - mu2) : 0.f;
    s_red[t] = d2 * d2;
    __syncthreads();
    for (int st = 64; st > 0; st >>= 1) { if (t < st) s_red[t] += s_red[t + st]; __syncthreads(); }
    float var2 = s_red[0] / 64.f;
    __syncthreads();
    float z2n = 0.f;
    if (t < 64) z2n = fmaxf(d2 * rsqrtf(var2 + 1e-5f) * ln2g[t] + ln2b[t], 0.f);
    s_red[t] = (t < 64) ? z2n * fc3w[t] : 0.f;
    __syncthreads();
    for (int st = 64; st > 0; st >>= 1) { if (t < st) s_red[t] += s_red[t + st]; __syncthreads(); }
    if (t == 0) out[b] = 1.f / (1.f + expf(-(s_red[0] + fc3b[0])));
}

// ---------------- launch ----------------
static inline int gr(int n) { return (n + 255) / 256; }

extern "C" void kernel_launch(void* const* d_in, const int* in_sizes, int n_in,
                              void* d_out, int out_size) {
    const float* x1   = (const float*)d_in[0];
    const int*   ei1  = (const int*)  d_in[1];
    const float* x2   = (const float*)d_in[3];
    const int*   ei2  = (const int*)  d_in[4];
    const float* w1l  = (const float*)d_in[5];
    const float* b1l  = (const float*)d_in[6];
    const float* w1r  = (const float*)d_in[7];
    const float* w2l  = (const float*)d_in[8];
    const float* b2l  = (const float*)d_in[9];
    const float* w2r  = (const float*)d_in[10];
    const float* fc1w = (const float*)d_in[11];
    const float* fc1b = (const float*)d_in[12];
    const float* ln1g = (const float*)d_in[13];
    const float* ln1b = (const float*)d_in[14];
    const float* fc2w = (const float*)d_in[15];
    const float* fc2b = (const float*)d_in[16];
    const float* ln2g = (const float*)d_in[17];
    const float* ln2b = (const float*)d_in[18];
    const float* fc3w = (const float*)d_in[19];
    const float* fc3b = (const float*)d_in[20];
    float* out = (float*)d_out;

    const int E1 = in_sizes[1] / 2;
    const int E2 = in_sizes[4] / 2;

    float *msg1, *h1, *o1, *msg2, *h2, *o2, *lastd, *featp, *z1raw;
    int *off1, *cur1, *el1, *off2, *cur2, *el2, *topkp, *bsum;
    cudaGetSymbolAddress((void**)&msg1, g_msg1);
    cudaGetSymbolAddress((void**)&h1,   g_h1);
    cudaGetSymbolAddress((void**)&o1,   g_o1);
    cudaGetSymbolAddress((void**)&msg2, g_msg2);
    cudaGetSymbolAddress((void**)&h2,   g_h2);
    cudaGetSymbolAddress((void**)&o2,   g_o2);
    cudaGetSymbolAddress((void**)&off1, g_off1);
    cudaGetSymbolAddress((void**)&cur1, g_cur1);
    cudaGetSymbolAddress((void**)&el1,  g_el1);
    cudaGetSymbolAddress((void**)&off2, g_off2);
    cudaGetSymbolAddress((void**)&cur2, g_cur2);
    cudaGetSymbolAddress((void**)&el2,  g_el2);
    cudaGetSymbolAddress((void**)&bsum, g_bsum);
    cudaGetSymbolAddress((void**)&lastd, g_lastd);
    cudaGetSymbolAddress((void**)&topkp, g_topk);
    cudaGetSymbolAddress((void**)&featp, g_feat);
    cudaGetSymbolAddress((void**)&z1raw, g_z1raw);

    const int NSCAN = (N1 + 255) / 256;   // 196

    // ---- CSR build (both graphs, merged launches) ----
    zero2<<<gr(N1 + N2), 256>>>(cur1, N1, cur2, N2);
    cnt2<<<gr(E1 + E2), 256>>>(ei1 + E1, E1, cur1, ei2 + E2, E2, cur2);
    scan_partial<<<NSCAN, 256>>>(cur1, off1, bsum, N1);
    scan_bsum<<<1, 256>>>(bsum, NSCAN);
    scan_fix<<<NSCAN, 256>>>(off1, bsum, cur1, N1);
    scank<<<1, 1024>>>(cur2, off2, N2);
    fill2<<<gr(E1 + E2), 256>>>(ei1, ei1 + E1, E1, off1, cur1, el1,
                                ei2, ei2 + E2, E2, off2, cur2, el2);

    // ---- layer 1 (both graphs): gather mean + linear ----
    gather_mean2<<<gr((N1 + N2) * 32), 256>>>(x1, off1, el1, x2, off2, el2, msg1, msg2);
    sage1_merged<<<G1B + G2B, 256>>>(msg1, x1, h1, msg2, x2, h2, w1l, b1l, w1r);

    // ---- layer 2: pre-transform then 64-dim gather with fused epilogue ----
    dual_linear<<<G1B + G2B, 256>>>(h1, msg1, h2, msg2, w2l, w2r);
    gather64_final<<<gr(N2 * 32), 256>>>(msg2, off2, el2, b2l, N2, o2, nullptr, nullptr);
    gather64_final<<<gr(N1 * 32), 256>>>(msg1, off1, el1, b2l, N1, o1,
                                         o2 + (size_t)(N2 - 1) * 64, lastd);

    // ---- exact stable top-50, selected distances ----
    topk_kernel<<<dim3(BGR, (NPG + 255) / 256), 256>>>(lastd, topkp);
    featgather<<<BGR * KSEL, 256>>>(topkp, o1, o2, featp);

    // ---- MLP head ----
    fc1_kernel<<<BGR * 128, 256>>>(featp, fc1w, fc1b, z1raw);
    mlp_tail<<<BGR, 128>>>(z1raw, ln1g, ln1b, fc2w, fc2b, ln2g, ln2b, fc3w, fc3b, out);
}

// round 7
// speedup vs baseline: 3.0824x; 1.0285x over previous
#include <cuda_runtime.h>
#include <cuda_bf16.h>
#include <math.h>

#define N1 50000
#define N2 199
#define FDIM 128
#define BGR 10
#define NPG 5000
#define KSEL 50
#define NFEAT (KSEL * N2)   // 9950
#define E1MAX 1000000
#define E2MAX 4000
#define G1B   ((N1 + 63) / 64)   // 782
#define G2B   ((N2 + 63) / 64)   // 4
#define NSCAN ((N1 + 255) / 256) // 196

// ---------------- packed f32x2 helpers ----------------
__device__ __forceinline__ unsigned long long pk2(float x, float y) {
    unsigned long long r;
    asm("mov.b64 %0, {%1, %2};" : "=l"(r) : "f"(x), "f"(y));
    return r;
}
__device__ __forceinline__ void fma2(unsigned long long& d,
                                     unsigned long long a, unsigned long long b) {
    asm("fma.rn.f32x2 %0, %1, %2, %0;" : "+l"(d) : "l"(a), "l"(b));
}
__device__ __forceinline__ float2 upk2(unsigned long long v) {
    float2 f;
    asm("mov.b64 {%0, %1}, %2;" : "=f"(f.x), "=f"(f.y) : "l"(v));
    return f;
}

// ---------------- scratch (device globals; no allocation) ----------------
__device__ float g_msg1[N1 * FDIM];   // layer1: mean(x) ; layer2: pp = h@[w2l|w2r]^T
__device__ float g_h1  [N1 * FDIM];
__device__ float g_o1  [N1 * 64];
__device__ float g_msg2[N2 * FDIM];
__device__ float g_h2  [N2 * FDIM];
__device__ float g_o2  [N2 * 64];
__device__ int   g_off1[N1 + 1];
__device__ int   g_cur1[N1];
__device__ int   g_el1 [E1MAX];
__device__ int   g_off2[N2 + 1];
__device__ int   g_cur2[N2];
__device__ int   g_el2 [E2MAX];
__device__ int   g_bsum[256];
__device__ float g_lastd[N1];
__device__ int   g_topk[BGR * KSEL];
__device__ float g_feat[BGR * NFEAT];
__device__ float g_z1raw[BGR * 128];

// ---------------- CSR build (merged for both graphs) ----------------
__global__ void zero2(int* a, int na, int* b, int nb_) {
    int i = blockIdx.x * blockDim.x + threadIdx.x;
    if (i < na) a[i] = 0;
    else if (i < na + nb_) b[i - na] = 0;
}

__global__ void cnt2(const int* __restrict__ d1, int e1, int* __restrict__ c1,
                     const int* __restrict__ d2, int e2, int* __restrict__ c2) {
    int i = blockIdx.x * blockDim.x + threadIdx.x;
    if (i < e1) atomicAdd(&c1[d1[i]], 1);
    else if (i < e1 + e2) atomicAdd(&c2[d2[i - e1]], 1);
}

// partial scan for graph1 (blocks 0..NSCAN-1); block NSCAN does graph2's full scan
__global__ void scan_partial(const int* __restrict__ cur1, int* __restrict__ off1,
                             int* __restrict__ bsum,
                             int* __restrict__ cur2, int* __restrict__ off2) {
    __shared__ int s[256];
    int tid = threadIdx.x;
    if (blockIdx.x < NSCAN) {
        int i = blockIdx.x * 256 + tid;
        s[tid] = (i < N1) ? cur1[i] : 0;
        __syncthreads();
        for (int d = 1; d < 256; d <<= 1) {
            int t = (tid >= d) ? s[tid - d] : 0;
            __syncthreads();
            s[tid] += t;
            __syncthreads();
        }
        if (i < N1) off1[i + 1] = s[tid];
        if (tid == 255) bsum[blockIdx.x] = s[255];
    } else {
        // graph2: full scan of 199 counts in one block
        s[tid] = (tid < N2) ? cur2[tid] : 0;
        __syncthreads();
        for (int d = 1; d < 256; d <<= 1) {
            int t = (tid >= d) ? s[tid - d] : 0;
            __syncthreads();
            s[tid] += t;
            __syncthreads();
        }
        if (tid < N2) { off2[tid + 1] = s[tid]; cur2[tid] = 0; }
        if (tid == 0) off2[0] = 0;
    }
}

// add exclusive block-sum prefix (computed in-block) and reset cur1
__global__ void scan_fix(int* __restrict__ off, const int* __restrict__ bsum,
                         int* __restrict__ cur) {
    __shared__ int s[256];
    int tid = threadIdx.x;
    s[tid] = (tid < blockIdx.x) ? bsum[tid] : 0;   // NSCAN <= 256
    __syncthreads();
    for (int st = 128; st > 0; st >>= 1) {
        if (tid < st) s[tid] += s[tid + st];
        __syncthreads();
    }
    int base = s[0];
    int i = blockIdx.x * 256 + tid;
    if (i < N1) { off[i + 1] += base; cur[i] = 0; }
    if (i == 0) off[0] = 0;
}

__global__ void fill2(const int* __restrict__ s1, const int* __restrict__ d1, int e1,
                      const int* __restrict__ off1, int* __restrict__ cur1, int* __restrict__ el1,
                      const int* __restrict__ s2, const int* __restrict__ d2, int e2,
                      const int* __restrict__ off2, int* __restrict__ cur2, int* __restrict__ el2) {
    int i = blockIdx.x * blockDim.x + threadIdx.x;
    if (i < e1) {
        int d = d1[i];
        int p = atomicAdd(&cur1[d], 1);
        el1[off1[d] + p] = s1[i];
    } else if (i < e1 + e2) {
        int j = i - e1;
        int d = d2[j];
        int p = atomicAdd(&cur2[d], 1);
        el2[off2[d] + p] = s2[j];
    }
}

// ---------------- layer-1 gather: mean of neighbor raw features (both graphs) ----------------
__global__ void gather_mean2(const float* __restrict__ x1, const int* __restrict__ off1,
                             const int* __restrict__ el1,
                             const float* __restrict__ x2, const int* __restrict__ off2,
                             const int* __restrict__ el2,
                             float* __restrict__ m1, float* __restrict__ m2) {
    int w = (blockIdx.x * blockDim.x + threadIdx.x) >> 5;
    const float* x; const int* off; const int* el; float* msg;
    if (w < N1) { x = x1; off = off1; el = el1; msg = m1; }
    else if (w < N1 + N2) { w -= N1; x = x2; off = off2; el = el2; msg = m2; }
    else return;
    int c = (threadIdx.x & 31) * 4;
    int beg = off[w], end = off[w + 1];
    float ax = 0.f, ay = 0.f, az = 0.f, aw = 0.f;
    for (int j = beg; j < end; j++) {
        int s = __ldg(el + j);
        float4 v = *reinterpret_cast<const float4*>(x + (size_t)s * FDIM + c);
        ax += v.x; ay += v.y; az += v.z; aw += v.w;
    }
    float inv = 1.f / fmaxf((float)(end - beg), 1.f);
    *reinterpret_cast<float4*>(msg + (size_t)w * FDIM + c) =
        make_float4(ax * inv, ay * inv, az * inv, aw * inv);
}

// ---------------- layer-1 linear (both graphs): h = relu(mean@wl^T + bl + x@wr^T) ----------------
// packed f32x2 FMA: 32 FFMA2 per k-step per thread (nodes packed in pairs).
__global__ __launch_bounds__(256)
void sage1_merged(const float* __restrict__ m1, const float* __restrict__ x1,
                  float* __restrict__ h1out,
                  const float* __restrict__ m2, const float* __restrict__ x2,
                  float* __restrict__ h2out,
                  const float* __restrict__ wl, const float* __restrict__ bl,
                  const float* __restrict__ wr) {
    constexpr int NT = 64, OPT = 4, OG = 32, NPT = 8;
    const float *mean, *x; float* out; int n, nb;
    if (blockIdx.x < G1B) { mean = m1; x = x1; out = h1out; n = N1; nb = blockIdx.x * NT; }
    else { mean = m2; x = x2; out = h2out; n = N2; nb = (blockIdx.x - G1B) * NT; }

    __shared__ __align__(16) float s_wl[32][132];
    __shared__ __align__(16) float s_wr[32][132];
    __shared__ __align__(16) float s_a[32][68];
    __shared__ __align__(16) float s_b[32][68];

    int tid = threadIdx.x;
    int og = tid % OG, ng = tid / OG;

    unsigned long long acc2[OPT][NPT / 2];
#pragma unroll
    for (int oi = 0; oi < OPT; oi++)
#pragma unroll
        for (int jp = 0; jp < NPT / 2; jp++) acc2[oi][jp] = 0ULL;

    for (int kk = 0; kk < FDIM; kk += 32) {
        for (int i = tid; i < 128 * 32; i += 256) {
            int o = i >> 5, k = i & 31;
            s_wl[k][o] = wl[o * FDIM + kk + k];
            s_wr[k][o] = wr[o * FDIM + kk + k];
        }
        for (int i = tid; i < NT * 32; i += 256) {
            int nn = i >> 5, k = i & 31;
            int gn = nb + nn;
            float av = 0.f, bv = 0.f;
            if (gn < n) {
                av = mean[(size_t)gn * FDIM + kk + k];
                bv = x[(size_t)gn * FDIM + kk + k];
            }
            s_a[k][nn] = av;
            s_b[k][nn] = bv;
        }
        __syncthreads();
#pragma unroll
        for (int k = 0; k < 32; k++) {
            float4 wl4 = *reinterpret_cast<const float4*>(&s_wl[k][og * OPT]);
            float4 wr4 = *reinterpret_cast<const float4*>(&s_wr[k][og * OPT]);
            unsigned long long wl2[4] = {pk2(wl4.x, wl4.x), pk2(wl4.y, wl4.y),
                                         pk2(wl4.z, wl4.z), pk2(wl4.w, wl4.w)};
            unsigned long long wr2[4] = {pk2(wr4.x, wr4.x), pk2(wr4.y, wr4.y),
                                         pk2(wr4.z, wr4.z), pk2(wr4.w, wr4.w)};
#pragma unroll
            for (int j0 = 0; j0 < NPT; j0 += 4) {
                ulonglong2 a2 = *reinterpret_cast<const ulonglong2*>(&s_a[k][ng * NPT + j0]);
                ulonglong2 b2 = *reinterpret_cast<const ulonglong2*>(&s_b[k][ng * NPT + j0]);
#pragma unroll
                for (int oi = 0; oi < OPT; oi++) {
                    fma2(acc2[oi][j0 / 2],     a2.x, wl2[oi]);
                    fma2(acc2[oi][j0 / 2 + 1], a2.y, wl2[oi]);
                    fma2(acc2[oi][j0 / 2],     b2.x, wr2[oi]);
                    fma2(acc2[oi][j0 / 2 + 1], b2.y, wr2[oi]);
                }
            }
        }
        __syncthreads();
    }
#pragma unroll
    for (int jp = 0; jp < NPT / 2; jp++) {
#pragma unroll
        for (int oi = 0; oi < OPT; oi++) {
            float2 v = upk2(acc2[oi][jp]);
            int o = og * OPT + oi;
            float bo = bl[o];
            int n0 = nb + ng * NPT + jp * 2;
            if (n0 < n)     out[(size_t)n0 * 128 + o]       = fmaxf(v.x + bo, 0.f);
            if (n0 + 1 < n) out[(size_t)(n0 + 1) * 128 + o] = fmaxf(v.y + bo, 0.f);
        }
    }
}

// ---------------- layer-2 pre-transform: pp = h @ [w2l | w2r]^T (both graphs) ----------------
__global__ __launch_bounds__(256)
void dual_linear(const float* __restrict__ h1in, float* __restrict__ pp1,
                 const float* __restrict__ h2in, float* __restrict__ pp2,
                 const float* __restrict__ w2l, const float* __restrict__ w2r) {
    constexpr int NT = 64, OPT = 4, OG = 32, NPT = 8;
    const float* h; float* pp; int n, nb;
    if (blockIdx.x < G1B) { h = h1in; pp = pp1; n = N1; nb = blockIdx.x * NT; }
    else { h = h2in; pp = pp2; n = N2; nb = (blockIdx.x - G1B) * NT; }

    __shared__ __align__(16) float s_w[32][132];
    __shared__ __align__(16) float s_b[32][68];

    int tid = threadIdx.x;
    int og = tid % OG, ng = tid / OG;

    unsigned long long acc2[OPT][NPT / 2];
#pragma unroll
    for (int oi = 0; oi < OPT; oi++)
#pragma unroll
        for (int jp = 0; jp < NPT / 2; jp++) acc2[oi][jp] = 0ULL;

    for (int kk = 0; kk < FDIM; kk += 32) {
        for (int i = tid; i < 128 * 32; i += 256) {
            int o = i >> 5, k = i & 31;
            s_w[k][o] = (o < 64) ? w2l[o * FDIM + kk + k] : w2r[(o - 64) * FDIM + kk + k];
        }
        for (int i = tid; i < NT * 32; i += 256) {
            int nn = i >> 5, k = i & 31;
            int gn = nb + nn;
            s_b[k][nn] = (gn < n) ? h[(size_t)gn * FDIM + kk + k] : 0.f;
        }
        __syncthreads();
#pragma unroll
        for (int k = 0; k < 32; k++) {
            float4 w4 = *reinterpret_cast<const float4*>(&s_w[k][og * OPT]);
            unsigned long long w2[4] = {pk2(w4.x, w4.x), pk2(w4.y, w4.y),
                                        pk2(w4.z, w4.z), pk2(w4.w, w4.w)};
#pragma unroll
            for (int j0 = 0; j0 < NPT; j0 += 4) {
                ulonglong2 b2 = *reinterpret_cast<const ulonglong2*>(&s_b[k][ng * NPT + j0]);
#pragma unroll
                for (int oi = 0; oi < OPT; oi++) {
                    fma2(acc2[oi][j0 / 2],     b2.x, w2[oi]);
                    fma2(acc2[oi][j0 / 2 + 1], b2.y, w2[oi]);
                }
            }
        }
        __syncthreads();
    }
#pragma unroll
    for (int jp = 0; jp < NPT / 2; jp++) {
#pragma unroll
        for (int oi = 0; oi < OPT; oi++) {
            float2 v = upk2(acc2[oi][jp]);
            int o = og * OPT + oi;
            int n0 = nb + ng * NPT + jp * 2;
            if (n0 < n)     pp[(size_t)n0 * 128 + o]       = v.x;
            if (n0 + 1 < n) pp[(size_t)(n0 + 1) * 128 + o] = v.y;
        }
    }
}

// ---------------- layer-2 gather + epilogue (+ optional fused lastdist) ----------------
__global__ void gather64_final(const float* __restrict__ pp, const int* __restrict__ off,
                               const int* __restrict__ el, const float* __restrict__ b2l,
                               int n, float* __restrict__ outp,
                               const float* __restrict__ bref, float* __restrict__ lastd) {
    int w = (blockIdx.x * blockDim.x + threadIdx.x) >> 5;
    if (w >= n) return;
    int lane = threadIdx.x & 31;
    int c = lane * 2;
    int beg = off[w], end = off[w + 1];
    float a0 = 0.f, a1 = 0.f;
    for (int j = beg; j < end; j++) {
        int s = __ldg(el + j);
        float2 v = *reinterpret_cast<const float2*>(pp + (size_t)s * 128 + c);
        a0 += v.x; a1 += v.y;
    }
    float inv = 1.f / fmaxf((float)(end - beg), 1.f);
    float2 r  = *reinterpret_cast<const float2*>(pp + (size_t)w * 128 + 64 + c);
    float2 bb = *reinterpret_cast<const float2*>(b2l + c);
    float o0 = fmaxf(a0 * inv + bb.x + r.x, 0.f);
    float o1 = fmaxf(a1 * inv + bb.y + r.y, 0.f);
    *reinterpret_cast<float2*>(outp + (size_t)w * 64 + c) = make_float2(o0, o1);
    if (lastd) {
        float2 bv = *reinterpret_cast<const float2*>(bref + c);
        float acc = o0 * o0 + o1 * o1 + bv.x * bv.x + bv.y * bv.y
                  - 2.f * (o0 * bv.x + o1 * bv.y);
#pragma unroll
        for (int m = 16; m >= 1; m >>= 1) acc += __shfl_xor_sync(0xffffffffu, acc, m);
        if (lane == 0) lastd[w] = sqrtf(fmaxf(acc, 0.f));
    }
}

// ---------------- exact stable top-50 per graph via rank counting ----------------
__global__ void topk_kernel(const float* __restrict__ lastd, int* __restrict__ topk) {
    __shared__ float s_v[NPG];
    int b = blockIdx.x;
    for (int i = threadIdx.x; i < NPG; i += 256) s_v[i] = lastd[b * NPG + i];
    __syncthreads();
    int cand = blockIdx.y * 256 + threadIdx.x;
    if (cand < NPG) {
        float v = s_v[cand];
        int rank = 0;
        for (int j = 0; j < NPG; j++) {
            float u = s_v[j];
            rank += (u > v) || (u == v && j < cand);
        }
        if (rank < KSEL) topk[b * KSEL + rank] = b * NPG + cand;
    }
}

// ---------------- gather 199 distances for each selected row ----------------
__global__ void featgather(const int* __restrict__ topk, const float* __restrict__ o1,
                           const float* __restrict__ o2, float* __restrict__ feat) {
    int idx = blockIdx.x;               // 0..499
    int row = topk[idx];
    __shared__ float s_a[64];
    __shared__ float s_a2;
    int t = threadIdx.x;
    if (t < 64) s_a[t] = o1[(size_t)row * 64 + t];
    __syncthreads();
    if (t == 0) {
        float s = 0.f;
        for (int k = 0; k < 64; k++) s += s_a[k] * s_a[k];
        s_a2 = s;
    }
    __syncthreads();
    if (t < N2) {
        const float* br = o2 + (size_t)t * 64;
        float dot = 0.f, b2 = 0.f;
#pragma unroll
        for (int k = 0; k < 64; k++) {
            float bv = br[k];
            dot += s_a[k] * bv;
            b2  += bv * bv;
        }
        float d2 = s_a2 + b2 - 2.f * dot;
        feat[idx * N2 + t] = sqrtf(fmaxf(d2, 0.f));
    }
}

// ---------------- fc1 ----------------
__global__ void fc1_kernel(const float* __restrict__ feat, const float* __restrict__ w,
                           const float* __restrict__ bias, float* __restrict__ z) {
    int b = blockIdx.x >> 7;
    int o = blockIdx.x & 127;
    const float* f  = feat + (size_t)b * NFEAT;
    const float* wr = w + (size_t)o * NFEAT;
    float acc = 0.f;
    for (int k = threadIdx.x; k < NFEAT; k += 256) acc += f[k] * wr[k];
    __shared__ float s[256];
    s[threadIdx.x] = acc;
    __syncthreads();
    for (int st = 128; st > 0; st >>= 1) {
        if (threadIdx.x < st) s[threadIdx.x] += s[threadIdx.x + st];
        __syncthreads();
    }
    if (threadIdx.x == 0) z[b * 128 + o] = s[0] + bias[o];
}

// ---------------- LN + relu + fc2 + LN + relu + fc3 + sigmoid ----------------
__global__ void mlp_tail(const float* __restrict__ z1raw,
                         const float* __restrict__ ln1g, const float* __restrict__ ln1b,
                         const float* __restrict__ fc2w, const float* __restrict__ fc2b,
                         const float* __restrict__ ln2g, const float* __restrict__ ln2b,
                         const float* __restrict__ fc3w, const float* __restrict__ fc3b,
                         float* __restrict__ out) {
    int b = blockIdx.x, t = threadIdx.x;
    __shared__ float s_z[128], s_red[128];

    float v = z1raw[b * 128 + t];
    s_red[t] = v;
    __syncthreads();
    for (int st = 64; st > 0; st >>= 1) { if (t < st) s_red[t] += s_red[t + st]; __syncthreads(); }
    float mu = s_red[0] / 128.f;
    __syncthreads();
    float d = v - mu;
    s_red[t] = d * d;
    __syncthreads();
    for (int st = 64; st > 0; st >>= 1) { if (t < st) s_red[t] += s_red[t + st]; __syncthreads(); }
    float var = s_red[0] / 128.f;
    __syncthreads();
    s_z[t] = fmaxf(d * rsqrtf(var + 1e-5f) * ln1g[t] + ln1b[t], 0.f);
    __syncthreads();

    float z2v = 0.f;
    if (t < 64) {
        float a = fc2b[t];
        for (int k = 0; k < 128; k++) a += s_z[k] * fc2w[t * 128 + k];
        z2v = a;
    }
    s_red[t] = (t < 64) ? z2v : 0.f;
    __syncthreads();
    for (int st = 64; st > 0; st >>= 1) { if (t < st) s_red[t] += s_red[t + st]; __syncthreads(); }
    float mu2 = s_red[0] / 64.f;
    __syncthreads();
    float d2 = (t < 64) ? (z2v - mu2) : 0.f;
    s_red[t] = d2 * d2;
    __syncthreads();
    for (int st = 64; st > 0; st >>= 1) { if (t < st) s_red[t] += s_red[t + st]; __syncthreads(); }
    float var2 = s_red[0] / 64.f;
    __syncthreads();
    float z2n = 0.f;
    if (t < 64) z2n = fmaxf(d2 * rsqrtf(var2 + 1e-5f) * ln2g[t] + ln2b[t], 0.f);
    s_red[t] = (t < 64) ? z2n * fc3w[t] : 0.f;
    __syncthreads();
    for (int st = 64; st > 0; st >>= 1) { if (t < st) s_red[t] += s_red[t + st]; __syncthreads(); }
    if (t == 0) out[b] = 1.f / (1.f + expf(-(s_red[0] + fc3b[0])));
}

// ---------------- launch ----------------
static inline int gr(int n) { return (n + 255) / 256; }

extern "C" void kernel_launch(void* const* d_in, const int* in_sizes, int n_in,
                              void* d_out, int out_size) {
    const float* x1   = (const float*)d_in[0];
    const int*   ei1  = (const int*)  d_in[1];
    const float* x2   = (const float*)d_in[3];
    const int*   ei2  = (const int*)  d_in[4];
    const float* w1l  = (const float*)d_in[5];
    const float* b1l  = (const float*)d_in[6];
    const float* w1r  = (const float*)d_in[7];
    const float* w2l  = (const float*)d_in[8];
    const float* b2l  = (const float*)d_in[9];
    const float* w2r  = (const float*)d_in[10];
    const float* fc1w = (const float*)d_in[11];
    const float* fc1b = (const float*)d_in[12];
    const float* ln1g = (const float*)d_in[13];
    const float* ln1b = (const float*)d_in[14];
    const float* fc2w = (const float*)d_in[15];
    const float* fc2b = (const float*)d_in[16];
    const float* ln2g = (const float*)d_in[17];
    const float* ln2b = (const float*)d_in[18];
    const float* fc3w = (const float*)d_in[19];
    const float* fc3b = (const float*)d_in[20];
    float* out = (float*)d_out;

    const int E1 = in_sizes[1] / 2;
    const int E2 = in_sizes[4] / 2;

    float *msg1, *h1, *o1, *msg2, *h2, *o2, *lastd, *featp, *z1raw;
    int *off1, *cur1, *el1, *off2, *cur2, *el2, *topkp, *bsum;
    cudaGetSymbolAddress((void**)&msg1, g_msg1);
    cudaGetSymbolAddress((void**)&h1,   g_h1);
    cudaGetSymbolAddress((void**)&o1,   g_o1);
    cudaGetSymbolAddress((void**)&msg2, g_msg2);
    cudaGetSymbolAddress((void**)&h2,   g_h2);
    cudaGetSymbolAddress((void**)&o2,   g_o2);
    cudaGetSymbolAddress((void**)&off1, g_off1);
    cudaGetSymbolAddress((void**)&cur1, g_cur1);
    cudaGetSymbolAddress((void**)&el1,  g_el1);
    cudaGetSymbolAddress((void**)&off2, g_off2);
    cudaGetSymbolAddress((void**)&cur2, g_cur2);
    cudaGetSymbolAddress((void**)&el2,  g_el2);
    cudaGetSymbolAddress((void**)&bsum, g_bsum);
    cudaGetSymbolAddress((void**)&lastd, g_lastd);
    cudaGetSymbolAddress((void**)&topkp, g_topk);
    cudaGetSymbolAddress((void**)&featp, g_feat);
    cudaGetSymbolAddress((void**)&z1raw, g_z1raw);

    // ---- CSR build (both graphs) ----
    zero2<<<gr(N1 + N2), 256>>>(cur1, N1, cur2, N2);
    cnt2<<<gr(E1 + E2), 256>>>(ei1 + E1, E1, cur1, ei2 + E2, E2, cur2);
    scan_partial<<<NSCAN + 1, 256>>>(cur1, off1, bsum, cur2, off2);
    scan_fix<<<NSCAN, 256>>>(off1, bsum, cur1);
    fill2<<<gr(E1 + E2), 256>>>(ei1, ei1 + E1, E1, off1, cur1, el1,
                                ei2, ei2 + E2, E2, off2, cur2, el2);

    // ---- layer 1 (both graphs): gather mean + linear ----
    gather_mean2<<<gr((N1 + N2) * 32), 256>>>(x1, off1, el1, x2, off2, el2, msg1, msg2);
    sage1_merged<<<G1B + G2B, 256>>>(msg1, x1, h1, msg2, x2, h2, w1l, b1l, w1r);

    // ---- layer 2: pre-transform then 64-dim gather with fused epilogue ----
    dual_linear<<<G1B + G2B, 256>>>(h1, msg1, h2, msg2, w2l, w2r);
    gather64_final<<<gr(N2 * 32), 256>>>(msg2, off2, el2, b2l, N2, o2, nullptr, nullptr);
    gather64_final<<<gr(N1 * 32), 256>>>(msg1, off1, el1, b2l, N1, o1,
                                         o2 + (size_t)(N2 - 1) * 64, lastd);

    // ---- exact stable top-50, selected distances ----
    topk_kernel<<<dim3(BGR, (NPG + 255) / 256), 256>>>(lastd, topkp);
    featgather<<<BGR * KSEL, 256>>>(topkp, o1, o2, featp);

    // ---- MLP head ----
    fc1_kernel<<<BGR * 128, 256>>>(featp, fc1w, fc1b, z1raw);
    mlp_tail<<<BGR, 128>>>(z1raw, ln1g, ln1b, fc2w, fc2b, ln2g, ln2b, fc3w, fc3b, out);
}